// round 7
// baseline (speedup 1.0000x reference)
#include <cuda_runtime.h>
#include <math.h>

#define NB 4
#define NC 31
#define NK 16                 // Hermitian half of C-spectrum
#define SLICE 16384           // 128*128
#define VOL   (NB*NC*SLICE)   // 2031616
#define PEN   (NB*SLICE)      // 65536 pencils

// ---------------- static scratch --------------------------------------------
__device__ float  g_Z[VOL];
__device__ float  g_M[VOL];       // M = mu1*X + G1 (for the CURRENT iter's numer)
__device__ float  g_G1[VOL];
__device__ float  g_Ph[2][VOL];
__device__ float  g_Pv[2][VOL];
__device__ float  g_Ps[VOL];
__device__ float2 g_S[NB*NK*SLICE];   // spectral working buffer

// ---------------- helpers ---------------------------------------------------
__device__ __forceinline__ float shrinkf(float x, float t) {
    return copysignf(fmaxf(fabsf(x) - t, 0.0f), x);
}
__device__ __forceinline__ float2 cadd(float2 a, float2 b){ return make_float2(a.x+b.x, a.y+b.y); }
__device__ __forceinline__ float2 csub(float2 a, float2 b){ return make_float2(a.x-b.x, a.y-b.y); }
__device__ __forceinline__ float2 cmuln(float2 d, float2 w){   // d * (wx - i*wy)
    return make_float2(d.x*w.x + d.y*w.y, d.y*w.x - d.x*w.y);
}
__device__ __forceinline__ float2 cmulp(float2 d, float2 w){   // d * (wx + i*wy)
    return make_float2(d.x*w.x - d.y*w.y, d.x*w.y + d.y*w.x);
}
__device__ __forceinline__ float2 shfl2(float2 v, int m){
    float2 r;
    r.x = __shfl_xor_sync(0xffffffffu, v.x, m);
    r.y = __shfl_xor_sync(0xffffffffu, v.y, m);
    return r;
}
// build flat [c][k] table: twck[c*NK+k] = (cos, -sin)(2*pi*k*c/31)
__device__ __forceinline__ void build_twck(float2* twck, int tid, int nthr){
    for (int e = tid; e < NC*NK; e += nthr){
        int c = e >> 4, k = e & 15;
        int m = (k * c) % NC;
        float s, co; sincospif((float)m * (2.f/31.f), &s, &co);
        twck[e] = make_float2(co, -s);
    }
}

// ---------------- warp-level 128-pt FFT (4 complex per lane) -----------------
__device__ __forceinline__ void wfft_fwd(float2 v[4], const float2* __restrict__ twd, int t){
    {   // hs=6
        float2 w0 = twd[t], w1 = twd[32 + t];
        float2 a = v[0], b = v[2]; v[0] = cadd(a,b); v[2] = cmuln(csub(a,b), w0);
        a = v[1]; b = v[3]; v[1] = cadd(a,b); v[3] = cmuln(csub(a,b), w1);
    }
    {   // hs=5
        float2 w = twd[2*t];
        float2 a = v[0], b = v[1]; v[0] = cadd(a,b); v[1] = cmuln(csub(a,b), w);
        a = v[2]; b = v[3]; v[2] = cadd(a,b); v[3] = cmuln(csub(a,b), w);
    }
    #pragma unroll
    for (int hs = 4; hs >= 0; hs--){
        int half = 1 << hs;
        float2 w = twd[(t & (half-1)) << (6 - hs)];
        bool up = (t & half) != 0;
        #pragma unroll
        for (int j = 0; j < 4; j++){
            float2 pv = shfl2(v[j], half);
            v[j] = up ? cmuln(csub(pv, v[j]), w) : cadd(v[j], pv);
        }
    }
}

__device__ __forceinline__ void wfft_inv(float2 v[4], const float2* __restrict__ twd, int t){
    #pragma unroll
    for (int hs = 0; hs <= 4; hs++){
        int half = 1 << hs;
        float2 w = twd[(t & (half-1)) << (6 - hs)];
        bool up = (t & half) != 0;
        #pragma unroll
        for (int j = 0; j < 4; j++){
            float2 u = up ? cmulp(v[j], w) : v[j];
            float2 pu = shfl2(u, half);
            v[j] = up ? csub(pu, u) : cadd(u, pu);
        }
    }
    {   // hs=5
        float2 w = twd[2*t];
        float2 tm = cmulp(v[1], w); float2 x0 = v[0]; v[0] = cadd(x0,tm); v[1] = csub(x0,tm);
        tm = cmulp(v[3], w); x0 = v[2]; v[2] = cadd(x0,tm); v[3] = csub(x0,tm);
    }
    {   // hs=6
        float2 w0 = twd[t], w1 = twd[32 + t];
        float2 tm = cmulp(v[2], w0); float2 x0 = v[0]; v[0] = cadd(x0,tm); v[2] = csub(x0,tm);
        tm = cmulp(v[3], w1); x0 = v[1]; v[1] = cadd(x0,tm); v[3] = csub(x0,tm);
    }
}

// ---------------- init ------------------------------------------------------
__global__ void k_init(const float* __restrict__ Y, float mu1_0) {
    int i = blockIdx.x * blockDim.x + threadIdx.x;
    if (i >= VOL) return;
    float y = Y[i];
    g_Z[i] = y;
    g_M[i] = mu1_0 * y;        // X=Y, G1=0 -> M = mu1*Y
    g_G1[i] = 0.f;
    g_Ph[0][i] = 0.f; g_Pv[0][i] = 0.f; g_Ps[i] = 0.f;
}

// ---------------- fused: pencil phase + real C-DFT + forward row FFT --------
// Phase-split: (1) pencil math -> numer staged to smem (low regs, high MLP),
// (2) 31-pt real DFT replayed from smem (F[16] regs live only here),
// (3) row FFT. numer buffer aliases the sF row-FFT staging buffer.
__global__ __launch_bounds__(256, 4) void k_cfwd_rows(int pp, float mu2,
                                                      float mu2p, float inv_mu2, float thr)
{
    __shared__ float2 twck[NC*NK];
    __shared__ float2 twd[64];
    __shared__ float  buf[NK*256*2];    // 32KB union: numer[31*256] | sF[16*256] float2
    float*  numer = buf;
    float2* sF    = (float2*)buf;

    int tid = threadIdx.x;
    build_twck(twck, tid, 256);
    if (tid < 64){ float s, c; sincospif((float)tid*(1.f/64.f), &s, &c); twd[tid] = make_float2(c, s); }
    __syncthreads();

    int p  = blockIdx.x * 256 + tid;
    int hw = p & 16383;
    int h  = hw >> 7, w = hw & 127;
    int ow1 = ((w + 1)   & 127) - w;
    int owm = ((w + 127) & 127) - w;
    int oh1 = ((((h + 1)   & 127) - h) << 7);
    int ohm = ((((h + 127) & 127) - h) << 7);
    int base = (p >> 14) * (NC * SLICE) + hw;

    const float* __restrict__ Ph_in  = g_Ph[pp];
    float*       __restrict__ Ph_out = g_Ph[pp ^ 1];
    const float* __restrict__ Pv_in  = g_Pv[pp];
    float*       __restrict__ Pv_out = g_Pv[pp ^ 1];

    float z0  = g_Z[base];
    float z30 = g_Z[base + 30 * SLICE];
    float As_prev;
    {
        float d  = z30 - z0;
        float g2 = g_Ps[base + 30 * SLICE] - mu2p * d;
        float q  = g2 * inv_mu2;
        As_prev  = shrinkf(d - q, thr) + q;
    }

    // ---- phase 1: pencil math, stage numer to smem (own column only) ----
    float zc = z0;
    for (int c = 0; c < NC; c++) {
        int i = base + c * SLICE;
        float znext = (c < 30) ? g_Z[i + SLICE] : z0;
        float zw1 = g_Z[i + ow1], zwm = g_Z[i + owm];
        float zh1 = g_Z[i + oh1], zhm = g_Z[i + ohm];

        float dh  = zc - zw1;
        float g2h = Ph_in[i] - mu2p * dh;
        float qh  = g2h * inv_mu2;
        float Ah  = shrinkf(dh - qh, thr) + qh;
        Ph_out[i] = mu2 * Ah;
        float dhm  = zwm - zc;
        float g2hm = Ph_in[i + owm] - mu2p * dhm;
        float qhm  = g2hm * inv_mu2;
        float Ahm  = shrinkf(dhm - qhm, thr) + qhm;

        float dv  = zc - zh1;
        float g2v = Pv_in[i] - mu2p * dv;
        float qv  = g2v * inv_mu2;
        float Av  = shrinkf(dv - qv, thr) + qv;
        Pv_out[i] = mu2 * Av;
        float dvm  = zhm - zc;
        float g2vm = Pv_in[i + ohm] - mu2p * dvm;
        float qvm  = g2vm * inv_mu2;
        float Avm  = shrinkf(dvm - qvm, thr) + qvm;

        float ds  = zc - znext;
        float g2s = g_Ps[i] - mu2p * ds;
        float qs  = g2s * inv_mu2;
        float As  = shrinkf(ds - qs, thr) + qs;
        g_Ps[i]   = mu2 * As;

        numer[c * 256 + tid] = g_M[i]
                    + mu2 * ((Ah - Ahm) + (Av - Avm) + (As - As_prev));
        As_prev = As;
        zc = znext;
    }

    // ---- phase 2: real 31-pt DFT from staged numer (own column reads) ----
    float2 F[NK];
    #pragma unroll
    for (int k = 0; k < NK; k++) F[k] = make_float2(0.f, 0.f);
    for (int c = 0; c < NC; c++) {
        float nu = numer[c * 256 + tid];
        F[0].x += nu;
        const float2* tc = twck + (c << 4);
        #pragma unroll
        for (int k = 1; k < NK; k++) {
            float2 t = tc[k];
            F[k].x = fmaf(nu, t.x, F[k].x);
            F[k].y = fmaf(nu, t.y, F[k].y);
        }
    }
    __syncthreads();   // all numer reads done before sF overwrites the buffer

    #pragma unroll
    for (int k = 0; k < NK; k++) sF[k*256 + tid] = F[k];
    __syncthreads();

    // ---- phase 3: forward row FFT: 32 tasks (16 k x 2 rows), 8 warps ----
    int wid = tid >> 5, t = tid & 31;
    int n_b = blockIdx.x >> 6;
    int h0  = (blockIdx.x & 63) << 1;
    #pragma unroll
    for (int task = wid; task < 32; task += 8){
        int k = task >> 1, r = task & 1;
        float2 v[4];
        #pragma unroll
        for (int j = 0; j < 4; j++) v[j] = sF[k*256 + r*128 + t + 32*j];
        wfft_fwd(v, twd, t);
        float2* dst = g_S + (size_t)(n_b*NK + k)*SLICE + (h0 + r)*128;
        #pragma unroll
        for (int j = 0; j < 4; j++) dst[t + 32*j] = v[j];
    }
}

// ---------------- fused: col fwd FFT + spectral divide + col inv FFT --------
__global__ __launch_bounds__(256) void k_ccols(float mu1, float mu2){
    __shared__ float2 twd[64];
    __shared__ float  d128s[128];   // 2-2cos(2*pi*brev(pos)/128), by POSITION
    __shared__ float2 sT[16*129];
    int tid = threadIdx.x;
    if (tid < 64){ float s, c; sincospif((float)tid*(1.f/64.f), &s, &c); twd[tid] = make_float2(c, s); }
    if (tid < 128){
        int f = __brev((unsigned)tid) >> 25;
        d128s[tid] = 2.f - 2.f * cospif((float)f * (1.f/64.f));
    }

    int s  = blockIdx.x >> 3;
    int w0 = (blockIdx.x & 7) << 4;
    int kc = s & (NK - 1);
    float dck = 2.f - 2.f * cospif((float)kc * (2.f/31.f));

    const float2* src = g_S + (size_t)s * SLICE + w0;
    for (int idx = tid; idx < 2048; idx += 256){
        int h = idx >> 4, wl = idx & 15;
        sT[wl*129 + h] = src[h*128 + wl];
    }
    __syncthreads();

    int wid = tid >> 5, t = tid & 31;
    #pragma unroll
    for (int ci = 0; ci < 2; ci++){
        int wl = wid*2 + ci;
        float2 v[4];
        #pragma unroll
        for (int j = 0; j < 4; j++) v[j] = sT[wl*129 + t + 32*j];
        wfft_fwd(v, twd, t);
        float dw = d128s[w0 + wl];
        #pragma unroll
        for (int j = 0; j < 4; j++){
            float sc = __fdividef(6.103515625e-05f,      // 1/16384
                                  mu1 + mu2 * (dck + d128s[t + 32*j] + dw));
            v[j].x *= sc; v[j].y *= sc;
        }
        wfft_inv(v, twd, t);
        #pragma unroll
        for (int j = 0; j < 4; j++) sT[wl*129 + t + 32*j] = v[j];
    }
    __syncthreads();

    float2* dst = g_S + (size_t)s * SLICE + w0;
    for (int idx = tid; idx < 2048; idx += 256){
        int h = idx >> 4, wl = idx & 15;
        dst[h*128 + wl] = sT[wl*129 + h];
    }
}

// ---------------- fused: inverse row FFT + Hermitian C-synthesis + update ---
__global__ __launch_bounds__(512, 2) void k_irows_cinv(const float* __restrict__ Y,
                                                       const float* __restrict__ inW,
                                                       float mu1, float mu1n,
                                                       float* __restrict__ out)
{
    __shared__ float2 twd[64];
    __shared__ float2 twck[NC*NK];
    __shared__ float2 sH[NK*128];
    int tid = threadIdx.x;
    if (tid < 64){ float s, c; sincospif((float)tid*(1.f/64.f), &s, &c); twd[tid] = make_float2(c, s); }
    build_twck(twck, tid, 512);
    __syncthreads();

    int n = blockIdx.x >> 7, h = blockIdx.x & 127;
    int wid = tid >> 5, t = tid & 31;
    {
        int k = wid;   // 16 warps <-> 16 k
        const float2* src = g_S + (size_t)(n*NK + k)*SLICE + h*128;
        float2 v[4];
        #pragma unroll
        for (int j = 0; j < 4; j++) v[j] = src[t + 32*j];
        wfft_inv(v, twd, t);
        #pragma unroll
        for (int j = 0; j < 4; j++) sH[k*128 + t + 32*j] = v[j];
    }
    __syncthreads();

    int w = tid & 127, cg = tid >> 7;   // 4 c-groups per pencil
    float H0;
    float Hx[NK-1], Hy[NK-1];
    const float i31 = 1.f/31.f, i31x2 = 2.f/31.f;
    H0 = sH[w].x * i31;
    #pragma unroll
    for (int k = 1; k < NK; k++){
        float2 v = sH[k*128 + w];
        Hx[k-1] = v.x * i31x2; Hy[k-1] = v.y * i31x2;
    }

    int c0 = cg * 8, c1 = (cg == 3) ? 31 : c0 + 8;
    int base = n * (NC * SLICE) + h*128 + w;
    if (out != nullptr) {
        for (int c = c0; c < c1; c++){
            float acc = H0;
            const float2* tc = twck + (c << 4);
            #pragma unroll
            for (int k = 1; k < NK; k++){
                float2 tt = tc[k];
                acc = fmaf(Hx[k-1], tt.x, acc);
                acc = fmaf(Hy[k-1], tt.y, acc);
            }
            out[base + c * SLICE] = acc;
        }
    } else {
        for (int c = c0; c < c1; c++){
            float acc = H0;
            const float2* tc = twck + (c << 4);
            #pragma unroll
            for (int k = 1; k < NK; k++){
                float2 tt = tc[k];
                acc = fmaf(Hx[k-1], tt.x, acc);
                acc = fmaf(Hy[k-1], tt.y, acc);
            }
            int i = base + c * SLICE;
            g_Z[i] = acc;
            float xw = inW[i], y = Y[i], g1 = g_G1[i];
            float x = __fdividef(fmaf(xw, y, fmaf(mu1, acc, -g1)), xw + mu1);
            float g1n = fmaf(mu1, x - acc, g1);
            g_G1[i] = g1n;
            g_M[i]  = fmaf(mu1n, x, g1n);
        }
    }
}

// ---------------- launch ----------------------------------------------------
extern "C" void kernel_launch(void* const* d_in, const int* in_sizes, int n_in,
                              void* d_out, int out_size) {
    const float* Y   = (const float*)d_in[0];
    const float* inW = (const float*)d_in[1];
    float* out = (float*)d_out;

    k_init<<<(VOL + 255) / 256, 256>>>(Y, 0.1f);

    double mu1d = 0.1, mu2d = 0.1, mu2pd = 0.0;
    const double lam = 0.1;

    for (int it = 0; it < 20; it++) {
        float mu1 = (float)mu1d, mu2 = (float)mu2d, mu2p = (float)mu2pd;
        float mu1n = (float)(mu1d * 1.05);
        float inv_mu2 = (float)(1.0 / mu2d);
        float thr = (float)(lam / mu2d);
        int pp = it & 1;

        k_cfwd_rows<<<PEN/256, 256>>>(pp, mu2, mu2p, inv_mu2, thr);
        k_ccols<<<NB*NK*8, 256>>>(mu1, mu2);
        k_irows_cinv<<<NB*128, 512>>>(Y, inW, mu1, mu1n, (it == 19) ? out : nullptr);

        mu2pd = mu2d;
        mu1d *= 1.05;
        mu2d *= 1.05;
    }
}

// round 8
// speedup vs baseline: 1.3064x; 1.3064x over previous
#include <cuda_runtime.h>
#include <math.h>

#define NB 4
#define NC 31
#define NK 16                 // Hermitian half of C-spectrum
#define SLICE 16384           // 128*128
#define VOL   (NB*NC*SLICE)   // 2031616
#define PEN   (NB*SLICE)      // 65536 pencils

// ---------------- static scratch --------------------------------------------
__device__ float  g_Z[VOL];
__device__ float  g_M[VOL];       // M = mu1*X + G1 (for the CURRENT iter's numer)
__device__ float  g_G1[VOL];
__device__ float  g_Ph[2][VOL];
__device__ float  g_Pv[2][VOL];
__device__ float  g_Ps[VOL];
__device__ float2 g_S[NB*NK*SLICE];   // spectral working buffer

// ---------------- helpers ---------------------------------------------------
__device__ __forceinline__ float shrinkf(float x, float t) {
    return copysignf(fmaxf(fabsf(x) - t, 0.0f), x);
}
__device__ __forceinline__ float2 cadd(float2 a, float2 b){ return make_float2(a.x+b.x, a.y+b.y); }
__device__ __forceinline__ float2 csub(float2 a, float2 b){ return make_float2(a.x-b.x, a.y-b.y); }
__device__ __forceinline__ float2 cmuln(float2 d, float2 w){   // d * (wx - i*wy)
    return make_float2(d.x*w.x + d.y*w.y, d.y*w.x - d.x*w.y);
}
__device__ __forceinline__ float2 cmulp(float2 d, float2 w){   // d * (wx + i*wy)
    return make_float2(d.x*w.x - d.y*w.y, d.x*w.y + d.y*w.x);
}
__device__ __forceinline__ float2 shfl2(float2 v, int m){
    float2 r;
    r.x = __shfl_xor_sync(0xffffffffu, v.x, m);
    r.y = __shfl_xor_sync(0xffffffffu, v.y, m);
    return r;
}
// build flat [c][k] table: twck[c*NK+k] = (cos, -sin)(2*pi*k*c/31)
__device__ __forceinline__ void build_twck(float2* twck, int tid, int nthr){
    for (int e = tid; e < NC*NK; e += nthr){
        int c = e >> 4, k = e & 15;
        int m = (k * c) % NC;
        float s, co; sincospif((float)m * (2.f/31.f), &s, &co);
        twck[e] = make_float2(co, -s);
    }
}

// ---------------- warp-level 128-pt FFT (4 complex per lane) -----------------
__device__ __forceinline__ void wfft_fwd(float2 v[4], const float2* __restrict__ twd, int t){
    {   // hs=6
        float2 w0 = twd[t], w1 = twd[32 + t];
        float2 a = v[0], b = v[2]; v[0] = cadd(a,b); v[2] = cmuln(csub(a,b), w0);
        a = v[1]; b = v[3]; v[1] = cadd(a,b); v[3] = cmuln(csub(a,b), w1);
    }
    {   // hs=5
        float2 w = twd[2*t];
        float2 a = v[0], b = v[1]; v[0] = cadd(a,b); v[1] = cmuln(csub(a,b), w);
        a = v[2]; b = v[3]; v[2] = cadd(a,b); v[3] = cmuln(csub(a,b), w);
    }
    #pragma unroll
    for (int hs = 4; hs >= 0; hs--){
        int half = 1 << hs;
        float2 w = twd[(t & (half-1)) << (6 - hs)];
        bool up = (t & half) != 0;
        #pragma unroll
        for (int j = 0; j < 4; j++){
            float2 pv = shfl2(v[j], half);
            v[j] = up ? cmuln(csub(pv, v[j]), w) : cadd(v[j], pv);
        }
    }
}

__device__ __forceinline__ void wfft_inv(float2 v[4], const float2* __restrict__ twd, int t){
    #pragma unroll
    for (int hs = 0; hs <= 4; hs++){
        int half = 1 << hs;
        float2 w = twd[(t & (half-1)) << (6 - hs)];
        bool up = (t & half) != 0;
        #pragma unroll
        for (int j = 0; j < 4; j++){
            float2 u = up ? cmulp(v[j], w) : v[j];
            float2 pu = shfl2(u, half);
            v[j] = up ? csub(pu, u) : cadd(u, pu);
        }
    }
    {   // hs=5
        float2 w = twd[2*t];
        float2 tm = cmulp(v[1], w); float2 x0 = v[0]; v[0] = cadd(x0,tm); v[1] = csub(x0,tm);
        tm = cmulp(v[3], w); x0 = v[2]; v[2] = cadd(x0,tm); v[3] = csub(x0,tm);
    }
    {   // hs=6
        float2 w0 = twd[t], w1 = twd[32 + t];
        float2 tm = cmulp(v[2], w0); float2 x0 = v[0]; v[0] = cadd(x0,tm); v[2] = csub(x0,tm);
        tm = cmulp(v[3], w1); x0 = v[1]; v[1] = cadd(x0,tm); v[3] = csub(x0,tm);
    }
}

// ---------------- init ------------------------------------------------------
__global__ void k_init(const float* __restrict__ Y, float mu1_0) {
    int i = blockIdx.x * blockDim.x + threadIdx.x;
    if (i >= VOL) return;
    float y = Y[i];
    g_Z[i] = y;
    g_M[i] = mu1_0 * y;        // X=Y, G1=0 -> M = mu1*Y
    g_G1[i] = 0.f;
    g_Ph[0][i] = 0.f; g_Pv[0][i] = 0.f; g_Ps[i] = 0.f;
}

// ---------------- fused: pencil phase + real C-DFT + forward row FFT --------
// 2 threads per pencil (c-range split), 128 pencils (one (n,h) row) per block.
// grid = 512 blocks x 256 threads -> 131K threads (2x the pencil count).
__global__ __launch_bounds__(256, 4) void k_cfwd_rows(int pp, float mu2,
                                                      float mu2p, float inv_mu2, float thr)
{
    __shared__ float2 twck[NC*NK];
    __shared__ float2 twd[64];
    __shared__ float  buf[NK*128*2];    // 16KB union: numer[31*128] | sF[16*128] float2
    float*  numer = buf;
    float2* sF    = (float2*)buf;

    int tid = threadIdx.x;
    build_twck(twck, tid, 256);
    if (tid < 64){ float s, c; sincospif((float)tid*(1.f/64.f), &s, &c); twd[tid] = make_float2(c, s); }
    __syncthreads();

    int pl = tid & 127;        // pencil within block (== w)
    int q  = tid >> 7;         // c-range half: 0 -> [0,16), 1 -> [16,31)
    int n  = blockIdx.x >> 7;
    int h  = blockIdx.x & 127;
    int w  = pl;

    int ow1 = ((w + 1)   & 127) - w;
    int owm = ((w + 127) & 127) - w;
    int oh1 = ((((h + 1)   & 127) - h) << 7);
    int ohm = ((((h + 127) & 127) - h) << 7);
    int base = n * (NC * SLICE) + (h << 7) + w;

    const float* __restrict__ Ph_in  = g_Ph[pp];
    float*       __restrict__ Ph_out = g_Ph[pp ^ 1];
    const float* __restrict__ Pv_in  = g_Pv[pp];
    float*       __restrict__ Pv_out = g_Pv[pp ^ 1];

    int c_lo = q ? 16 : 0;
    int c_hi = q ? 31 : 16;
    int cprev = q ? 15 : 30;

    // boundary As_prev at c = c_lo-1 (mod 31)
    float z_lo = g_Z[base + c_lo * SLICE];
    float As_prev;
    {
        float zp = g_Z[base + cprev * SLICE];
        float d  = zp - z_lo;
        float g2 = g_Ps[base + cprev * SLICE] - mu2p * d;
        float qq = g2 * inv_mu2;
        As_prev  = shrinkf(d - qq, thr) + qq;
    }

    // ---- phase 1: pencil math for this thread's c-range ----
    float zc = z_lo;
    for (int c = c_lo; c < c_hi; c++) {
        int i = base + c * SLICE;
        int cn = (c == 30) ? 0 : c + 1;
        float znext = g_Z[base + cn * SLICE];
        float zw1 = g_Z[i + ow1], zwm = g_Z[i + owm];
        float zh1 = g_Z[i + oh1], zhm = g_Z[i + ohm];

        float dh  = zc - zw1;
        float g2h = Ph_in[i] - mu2p * dh;
        float qh  = g2h * inv_mu2;
        float Ah  = shrinkf(dh - qh, thr) + qh;
        Ph_out[i] = mu2 * Ah;
        float dhm  = zwm - zc;
        float g2hm = Ph_in[i + owm] - mu2p * dhm;
        float qhm  = g2hm * inv_mu2;
        float Ahm  = shrinkf(dhm - qhm, thr) + qhm;

        float dv  = zc - zh1;
        float g2v = Pv_in[i] - mu2p * dv;
        float qv  = g2v * inv_mu2;
        float Av  = shrinkf(dv - qv, thr) + qv;
        Pv_out[i] = mu2 * Av;
        float dvm  = zhm - zc;
        float g2vm = Pv_in[i + ohm] - mu2p * dvm;
        float qvm  = g2vm * inv_mu2;
        float Avm  = shrinkf(dvm - qvm, thr) + qvm;

        float ds  = zc - znext;
        float g2s = g_Ps[i] - mu2p * ds;
        float qs  = g2s * inv_mu2;
        float As  = shrinkf(ds - qs, thr) + qs;
        g_Ps[i]   = mu2 * As;

        numer[c * 128 + pl] = g_M[i]
                    + mu2 * ((Ah - Ahm) + (Av - Avm) + (As - As_prev));
        As_prev = As;
        zc = znext;
    }
    __syncthreads();

    // ---- phase 2: real 31-pt DFT; thread q computes k in [8q, 8q+8) ----
    // twck[c*16+0] = (1,0), so the uniform FMA path is exact for k=0.
    float2 F[8];
    #pragma unroll
    for (int kk = 0; kk < 8; kk++) F[kk] = make_float2(0.f, 0.f);
    int k0 = q << 3;
    for (int c = 0; c < NC; c++) {
        float nu = numer[c * 128 + pl];
        const float2* tc = twck + (c << 4) + k0;
        #pragma unroll
        for (int kk = 0; kk < 8; kk++) {
            float2 t = tc[kk];
            F[kk].x = fmaf(nu, t.x, F[kk].x);
            F[kk].y = fmaf(nu, t.y, F[kk].y);
        }
    }
    __syncthreads();   // all numer reads done before sF overwrites the buffer

    #pragma unroll
    for (int kk = 0; kk < 8; kk++) sF[(k0 + kk)*128 + pl] = F[kk];
    __syncthreads();

    // ---- phase 3: forward row FFT: 16 k-tasks, 8 warps (2 each) ----
    int wid = tid >> 5, t = tid & 31;
    #pragma unroll
    for (int ki = 0; ki < 2; ki++){
        int k = wid + ki * 8;
        float2 v[4];
        #pragma unroll
        for (int j = 0; j < 4; j++) v[j] = sF[k*128 + t + 32*j];
        wfft_fwd(v, twd, t);
        float2* dst = g_S + (size_t)(n*NK + k)*SLICE + (h << 7);
        #pragma unroll
        for (int j = 0; j < 4; j++) dst[t + 32*j] = v[j];
    }
}

// ---------------- fused: col fwd FFT + spectral divide + col inv FFT --------
__global__ __launch_bounds__(256) void k_ccols(float mu1, float mu2){
    __shared__ float2 twd[64];
    __shared__ float  d128s[128];   // 2-2cos(2*pi*brev(pos)/128), by POSITION
    __shared__ float2 sT[16*129];
    int tid = threadIdx.x;
    if (tid < 64){ float s, c; sincospif((float)tid*(1.f/64.f), &s, &c); twd[tid] = make_float2(c, s); }
    if (tid < 128){
        int f = __brev((unsigned)tid) >> 25;
        d128s[tid] = 2.f - 2.f * cospif((float)f * (1.f/64.f));
    }

    int s  = blockIdx.x >> 3;
    int w0 = (blockIdx.x & 7) << 4;
    int kc = s & (NK - 1);
    float dck = 2.f - 2.f * cospif((float)kc * (2.f/31.f));

    const float2* src = g_S + (size_t)s * SLICE + w0;
    for (int idx = tid; idx < 2048; idx += 256){
        int h = idx >> 4, wl = idx & 15;
        sT[wl*129 + h] = src[h*128 + wl];
    }
    __syncthreads();

    int wid = tid >> 5, t = tid & 31;
    #pragma unroll
    for (int ci = 0; ci < 2; ci++){
        int wl = wid*2 + ci;
        float2 v[4];
        #pragma unroll
        for (int j = 0; j < 4; j++) v[j] = sT[wl*129 + t + 32*j];
        wfft_fwd(v, twd, t);
        float dw = d128s[w0 + wl];
        #pragma unroll
        for (int j = 0; j < 4; j++){
            float sc = __fdividef(6.103515625e-05f,      // 1/16384
                                  mu1 + mu2 * (dck + d128s[t + 32*j] + dw));
            v[j].x *= sc; v[j].y *= sc;
        }
        wfft_inv(v, twd, t);
        #pragma unroll
        for (int j = 0; j < 4; j++) sT[wl*129 + t + 32*j] = v[j];
    }
    __syncthreads();

    float2* dst = g_S + (size_t)s * SLICE + w0;
    for (int idx = tid; idx < 2048; idx += 256){
        int h = idx >> 4, wl = idx & 15;
        dst[h*128 + wl] = sT[wl*129 + h];
    }
}

// ---------------- fused: inverse row FFT + Hermitian C-synthesis + update ---
__global__ __launch_bounds__(512, 2) void k_irows_cinv(const float* __restrict__ Y,
                                                       const float* __restrict__ inW,
                                                       float mu1, float mu1n,
                                                       float* __restrict__ out)
{
    __shared__ float2 twd[64];
    __shared__ float2 twck[NC*NK];
    __shared__ float2 sH[NK*128];
    int tid = threadIdx.x;
    if (tid < 64){ float s, c; sincospif((float)tid*(1.f/64.f), &s, &c); twd[tid] = make_float2(c, s); }
    build_twck(twck, tid, 512);
    __syncthreads();

    int n = blockIdx.x >> 7, h = blockIdx.x & 127;
    int wid = tid >> 5, t = tid & 31;
    {
        int k = wid;   // 16 warps <-> 16 k
        const float2* src = g_S + (size_t)(n*NK + k)*SLICE + h*128;
        float2 v[4];
        #pragma unroll
        for (int j = 0; j < 4; j++) v[j] = src[t + 32*j];
        wfft_inv(v, twd, t);
        #pragma unroll
        for (int j = 0; j < 4; j++) sH[k*128 + t + 32*j] = v[j];
    }
    __syncthreads();

    int w = tid & 127, cg = tid >> 7;   // 4 c-groups per pencil
    float H0;
    float Hx[NK-1], Hy[NK-1];
    const float i31 = 1.f/31.f, i31x2 = 2.f/31.f;
    H0 = sH[w].x * i31;
    #pragma unroll
    for (int k = 1; k < NK; k++){
        float2 v = sH[k*128 + w];
        Hx[k-1] = v.x * i31x2; Hy[k-1] = v.y * i31x2;
    }

    int c0 = cg * 8, c1 = (cg == 3) ? 31 : c0 + 8;
    int base = n * (NC * SLICE) + h*128 + w;
    if (out != nullptr) {
        for (int c = c0; c < c1; c++){
            float acc = H0;
            const float2* tc = twck + (c << 4);
            #pragma unroll
            for (int k = 1; k < NK; k++){
                float2 tt = tc[k];
                acc = fmaf(Hx[k-1], tt.x, acc);
                acc = fmaf(Hy[k-1], tt.y, acc);
            }
            out[base + c * SLICE] = acc;
        }
    } else {
        for (int c = c0; c < c1; c++){
            float acc = H0;
            const float2* tc = twck + (c << 4);
            #pragma unroll
            for (int k = 1; k < NK; k++){
                float2 tt = tc[k];
                acc = fmaf(Hx[k-1], tt.x, acc);
                acc = fmaf(Hy[k-1], tt.y, acc);
            }
            int i = base + c * SLICE;
            g_Z[i] = acc;
            float xw = inW[i], y = Y[i], g1 = g_G1[i];
            float x = __fdividef(fmaf(xw, y, fmaf(mu1, acc, -g1)), xw + mu1);
            float g1n = fmaf(mu1, x - acc, g1);
            g_G1[i] = g1n;
            g_M[i]  = fmaf(mu1n, x, g1n);
        }
    }
}

// ---------------- launch ----------------------------------------------------
extern "C" void kernel_launch(void* const* d_in, const int* in_sizes, int n_in,
                              void* d_out, int out_size) {
    const float* Y   = (const float*)d_in[0];
    const float* inW = (const float*)d_in[1];
    float* out = (float*)d_out;

    k_init<<<(VOL + 255) / 256, 256>>>(Y, 0.1f);

    double mu1d = 0.1, mu2d = 0.1, mu2pd = 0.0;
    const double lam = 0.1;

    for (int it = 0; it < 20; it++) {
        float mu1 = (float)mu1d, mu2 = (float)mu2d, mu2p = (float)mu2pd;
        float mu1n = (float)(mu1d * 1.05);
        float inv_mu2 = (float)(1.0 / mu2d);
        float thr = (float)(lam / mu2d);
        int pp = it & 1;

        k_cfwd_rows<<<NB*128, 256>>>(pp, mu2, mu2p, inv_mu2, thr);
        k_ccols<<<NB*NK*8, 256>>>(mu1, mu2);
        k_irows_cinv<<<NB*128, 512>>>(Y, inW, mu1, mu1n, (it == 19) ? out : nullptr);

        mu2pd = mu2d;
        mu1d *= 1.05;
        mu2d *= 1.05;
    }
}